// round 7
// baseline (speedup 1.0000x reference)
#include <cuda_runtime.h>
#include <math.h>

#define NB 64
#define NK 8
#define NV 50257
#define NR (NB*NK)                 // 512 rows
#define OUT_TOK (NB*(NK+1))        // 576
#define FUSED_OFF (OUT_TOK + NB)   // 640

#define GRID (2*NR)                // 1024 CTAs
#define NCPR 16                    // CTAs per batch row in stage B
#define CHUNK 3144                 // NCPR*CHUNK >= NV; keeps smem ~12.6KB

// Scratch (device globals: no allocation allowed)
__device__ float g_p[2*NR];        // [0..NR): p_llm, [NR..2NR): p_base
__device__ int   g_sel[NB];        // selected flat row index (b*K + rp)
__device__ int   g_fill[NB];       // output slot for recovered token, or -1
__device__ int   g_cnt1 = 0;       // stage A completion counter (self-resetting)
__device__ int   g_cnt2 = 0;       // stage B completion counter (self-resetting)
__device__ int   g_go   = 0;       // stage A->B release flag (self-resetting)
// stage B cross-CTA reduction scratch (reset by stage A tail each replay)
__device__ float              g_sum[NB];
__device__ unsigned long long g_amax[NB];
__device__ int                g_arrive[NB];
__device__ int                g_flag[NB];
__device__ float              g_L[NB];

// monotone float->uint key (total order matching float compare)
__device__ __forceinline__ unsigned int fkey(float f) {
    unsigned int u = __float_as_uint(f);
    return (u & 0x80000000u) ? ~u : (u | 0x80000000u);
}

// ---------------------------------------------------------------------------
// One persistent kernel, 1024 CTAs x 256 threads, all co-resident
// (__launch_bounds__(256,8): 8 blocks/SM reg-wise; smem 12.7KB -> 17/SM;
//  1024 <= 148*7 scheduler placement -> device-wide spins cannot deadlock).
//
// Stage A: per-(row,stream) sumexp + draft-token prob (phase1).
//          Last CTA runs accept/prefix logic (phase2), resets stage B
//          scratch, releases g_go.
// Stage B: CTA g -> (b = g/16, chunk = g%16) computes y = U*t + W*(s-b) for
//          its ~3.1K-element chunk, stages y in smem, combines sumexp/argmax
//          via global atomics, last arriver per row finalizes L and the
//          recovered token, then all 16 CTAs write y - L from smem.
// ---------------------------------------------------------------------------
__global__ __launch_bounds__(256, 8)
void fused_kernel(const float* __restrict__ tgt,
                  const float* __restrict__ base,
                  const float* __restrict__ steer,
                  const int*   __restrict__ draft,
                  const int*   __restrict__ ndraft,
                  float U, float W,
                  float* __restrict__ out)
{
    const int TPB = 256;
    const int tid = threadIdx.x;
    const int g   = blockIdx.x;

    __shared__ float sy[CHUNK];          // stage B staging
    __shared__ float shs[TPB / 32];
    __shared__ float shm[TPB / 32];
    __shared__ int   shi[TPB / 32];
    __shared__ float sh_L;
    __shared__ int   lastFlag;

    // ======================= Stage A: phase1 =============================
    {
        const int row    = g >> 1;
        const int stream = g & 1;
        const float* __restrict__ src =
            (stream ? base : tgt) + (size_t)row * NV;

        const int pre = (4 - ((row * NV) & 3)) & 3;   // align to 16B
        float s0 = 0.f, s1 = 0.f, s2 = 0.f, s3 = 0.f;
        if (tid < pre) s0 += __expf(src[tid]);

        const int nvec = (NV - pre) >> 2;
        const float4* __restrict__ pv = reinterpret_cast<const float4*>(src + pre);
        #pragma unroll 4
        for (int i = tid; i < nvec; i += TPB) {
            float4 v = pv[i];
            s0 += __expf(v.x); s1 += __expf(v.y);
            s2 += __expf(v.z); s3 += __expf(v.w);
        }
        const int done = pre + (nvec << 2);
        if (tid < NV - done) s1 += __expf(src[done + tid]);

        float s = (s0 + s1) + (s2 + s3);
        #pragma unroll
        for (int o = 16; o > 0; o >>= 1) s += __shfl_down_sync(0xffffffffu, s, o);
        if ((tid & 31) == 0) shs[tid >> 5] = s;
        __syncthreads();
        if (tid == 0) {
            float tot = 0.f;
            #pragma unroll
            for (int w = 0; w < TPB / 32; ++w) tot += shs[w];
            const int idx = draft[row];
            g_p[stream * NR + row] = expf(src[idx]) / tot;
        }
    }

    // =================== Stage A tail: phase2 + release ==================
    __threadfence();
    if (tid == 0) {
        const int c = atomicAdd(&g_cnt1, 1);
        lastFlag = (c == GRID - 1);
        if (lastFlag) g_cnt1 = 0;              // reset for next graph replay
    }
    __syncthreads();
    if (lastFlag) {
        if (tid < NB) {
            const int b = tid;
            const int num = ndraft[b];

            int cnt = 0;
            for (int k = 0; k < NK; ++k) {
                if (k >= num) break;                          // valid = pos < num
                const float pl = g_p[b * NK + k];
                const float pb = g_p[NR + b * NK + k];
                if (!(pl > 0.6f * (pb + 1e-10f))) break;      // accept test
                ++cnt;
            }

            for (int k = 0; k < NK; ++k)
                out[b * (NK + 1) + k] = (k < cnt) ? (float)draft[b * NK + k] : -1.0f;
            out[b * (NK + 1) + NK] = -1.0f;                   // bonus (disabled)
            out[OUT_TOK + b] = (float)cnt;                    // cnt output

            const int rp = cnt < (NK - 1) ? cnt : (NK - 1);
            g_sel[b]  = b * NK + rp;
            g_fill[b] = (cnt < num) ? (b * (NK + 1) + cnt) : -1;

            // reset stage B cross-CTA scratch for this replay
            g_sum[b]    = 0.f;
            g_amax[b]   = 0ull;
            g_arrive[b] = 0;
            g_flag[b]   = 0;
            __threadfence();
        }
        __syncthreads();
        if (tid == 0) atomicExch(&g_go, 1);    // release
    }
    // device-wide wait for phase2 results
    if (tid == 0) {
        while (atomicAdd(&g_go, 0) == 0) __nanosleep(32);
    }
    __syncthreads();
    __threadfence();                            // acquire

    // ======================= Stage B: phase3 =============================
    {
        const int b     = g >> 4;              // / NCPR
        const int chunk = g & 15;              // % NCPR
        const int row = g_sel[b];
        const int c0 = chunk * CHUNK;
        const int c1 = (c0 + CHUNK < NV) ? (c0 + CHUNK) : NV;
        const size_t rb = (size_t)row * NV;
        const float* __restrict__ pt = tgt   + rb;
        const float* __restrict__ pb = base  + rb;
        const float* __restrict__ ps = steer + rb;

        float m = -INFINITY; int mi = 0; float s = 0.f;

        const int pre = (4 - (int)((rb + c0) & 3)) & 3;
        if (tid < pre && c0 + tid < c1) {
            const int e = c0 + tid;
            float t = pt[e];  if (isnan(t))  t  = -100.f;
            float bb = pb[e]; if (isnan(bb)) bb = -100.f;
            float ss = ps[e]; if (isnan(ss)) ss = -100.f;
            const float y = U * t + W * (ss - bb);
            sy[e - c0] = y; s += __expf(y);
            if (y > m) { m = y; mi = e; }
        }

        const int nvec = (c1 - c0 - pre) >> 2;
        const float4* __restrict__ vt = reinterpret_cast<const float4*>(pt + c0 + pre);
        const float4* __restrict__ vb = reinterpret_cast<const float4*>(pb + c0 + pre);
        const float4* __restrict__ vs = reinterpret_cast<const float4*>(ps + c0 + pre);
        #pragma unroll 2
        for (int i = tid; i < nvec; i += TPB) {
            float4 a = vt[i], c = vb[i], d = vs[i];
            if (isnan(a.x)) a.x = -100.f; if (isnan(a.y)) a.y = -100.f;
            if (isnan(a.z)) a.z = -100.f; if (isnan(a.w)) a.w = -100.f;
            if (isnan(c.x)) c.x = -100.f; if (isnan(c.y)) c.y = -100.f;
            if (isnan(c.z)) c.z = -100.f; if (isnan(c.w)) c.w = -100.f;
            if (isnan(d.x)) d.x = -100.f; if (isnan(d.y)) d.y = -100.f;
            if (isnan(d.z)) d.z = -100.f; if (isnan(d.w)) d.w = -100.f;
            const int e = c0 + pre + 4 * i;          // global element index
            const int l = e - c0;                    // smem index
            const float y0 = U * a.x + W * (d.x - c.x);
            const float y1 = U * a.y + W * (d.y - c.y);
            const float y2 = U * a.z + W * (d.z - c.z);
            const float y3 = U * a.w + W * (d.w - c.w);
            sy[l]     = y0; sy[l + 1] = y1;
            sy[l + 2] = y2; sy[l + 3] = y3;
            s += (__expf(y0) + __expf(y1)) + (__expf(y2) + __expf(y3));
            if (y0 > m) { m = y0; mi = e; }
            if (y1 > m) { m = y1; mi = e + 1; }
            if (y2 > m) { m = y2; mi = e + 2; }
            if (y3 > m) { m = y3; mi = e + 3; }
        }
        const int done = c0 + pre + (nvec << 2);
        if (done + tid < c1) {
            const int e = done + tid;
            float t = pt[e];  if (isnan(t))  t  = -100.f;
            float bb = pb[e]; if (isnan(bb)) bb = -100.f;
            float ss = ps[e]; if (isnan(ss)) ss = -100.f;
            const float y = U * t + W * (ss - bb);
            sy[e - c0] = y; s += __expf(y);
            if (y > m) { m = y; mi = e; }
        }

        // block reductions: sum and (max, first-index argmax)
        #pragma unroll
        for (int o = 16; o > 0; o >>= 1) {
            s += __shfl_down_sync(0xffffffffu, s, o);
            float m2 = __shfl_down_sync(0xffffffffu, m, o);
            int   i2 = __shfl_down_sync(0xffffffffu, mi, o);
            if (m2 > m || (m2 == m && i2 < mi)) { m = m2; mi = i2; }
        }
        if ((tid & 31) == 0) { shs[tid >> 5] = s; shm[tid >> 5] = m; shi[tid >> 5] = mi; }
        __syncthreads();

        if (tid == 0) {
            float tot = 0.f;
            float M = shm[0]; int MI = shi[0];
            #pragma unroll
            for (int w = 0; w < TPB / 32; ++w) {
                tot += shs[w];
                if (shm[w] > M || (shm[w] == M && shi[w] < MI)) { M = shm[w]; MI = shi[w]; }
            }
            atomicAdd(&g_sum[b], tot);
            const unsigned long long key =
                ((unsigned long long)fkey(M) << 32) |
                (unsigned long long)(0xFFFFFFFFu - (unsigned int)MI);
            atomicMax(&g_amax[b], key);
            __threadfence();
            const int old = atomicAdd(&g_arrive[b], 1);
            if (old == NCPR - 1) {
                const float L = logf(g_sum[b]);
                g_L[b] = L;
                const int f = g_fill[b];
                if (f >= 0) {
                    const unsigned long long k = g_amax[b];
                    const int idx = (int)(0xFFFFFFFFu - (unsigned int)(k & 0xFFFFFFFFull));
                    out[f] = (float)idx;            // recovered token
                }
                __threadfence();
                atomicExch(&g_flag[b], 1);
                sh_L = L;
            } else {
                while (atomicAdd(&g_flag[b], 0) == 0) __nanosleep(32);
                __threadfence();
                sh_L = g_L[b];
            }
        }
        __syncthreads();
        const float L = sh_L;

        // write normalized log-probs from smem (coalesced)
        float* __restrict__ fo = out + FUSED_OFF + (size_t)b * NV;
        for (int i = c0 + tid; i < c1; i += TPB) fo[i] = sy[i - c0] - L;
    }

    // =================== epilogue: reset g_go for replay =================
    __threadfence();
    if (tid == 0) {
        const int c = atomicAdd(&g_cnt2, 1);
        if (c == GRID - 1) {        // last CTA: everyone has passed the spin
            g_cnt2 = 0;
            atomicExch(&g_go, 0);
        }
    }
}

// ---------------------------------------------------------------------------
extern "C" void kernel_launch(void* const* d_in, const int* in_sizes, int n_in,
                              void* d_out, int out_size)
{
    const float* tgt    = (const float*)d_in[0];
    const float* base   = (const float*)d_in[1];
    const float* steer  = (const float*)d_in[2];
    const int*   draft  = (const int*)d_in[3];
    const int*   ndraft = (const int*)d_in[4];
    // d_in[5] = bonus_token_ids: unused (ENABLE_BONUS == False)
    float* out = (float*)d_out;

    // Collapse the T=20 costeer recursion to scalar coefficients (double).
    // lp_t = log_softmax(u_t * llm_log + v_t * delta); u_t == 1 exactly.
    double Qu = 0.0, u = 1.0, Qv = 0.0, v = 0.0;
    for (int t = 1; t <= 20; ++t) {
        Qu += 2.0 * (u - 1.0);                 // ALPHA * (u - 1)
        Qv += 2.0 * v + 1.5;                   // ALPHA * v + BETA
        const double denom = 2.0 * t + 0.1;    // t*LAM + 1/ETA
        const double un = (2.0 * t + Qu + u / 10.0) / denom;
        const double vn = (Qv + v / 10.0) / denom;
        u = un; v = vn;
    }
    const float Uf = (float)u;
    const float Wf = (float)v;

    fused_kernel<<<GRID, 256>>>(tgt, base, steer, draft, ndraft, Uf, Wf, out);
}

// round 10
// speedup vs baseline: 1.0386x; 1.0386x over previous
#include <cuda_runtime.h>
#include <math.h>

#define NB 64
#define NK 8
#define NV 50257
#define NR (NB*NK)                 // 512 rows
#define OUT_TOK (NB*(NK+1))        // 576
#define FUSED_OFF (OUT_TOK + NB)   // 640

#define GRID (2*NR)                // 1024 CTAs
#define NCPR 16                    // CTAs per batch (stage A and stage B)
#define CHUNK 3144                 // NCPR*CHUNK >= NV; smem ~12.6KB

// Scratch (device globals: no allocation allowed; zero-initialized)
__device__ float g_p[2*NR];        // [0..NR): p_llm, [NR..2NR): p_base
__device__ int   g_sel[NB];        // selected flat row index (b*K + rp)
__device__ int   g_fill[NB];       // output slot for recovered token, or -1
__device__ int   g_doneA[NB];      // per-batch stage A counter (self-reset)
__device__ int   g_go[NB];         // per-batch A->B release flag
__device__ int   g_cnt2[NB];       // per-batch stage B epilogue counter
// stage B cross-CTA reduction scratch (reset by batch's phase2 leader)
__device__ float              g_sum[NB];
__device__ unsigned long long g_amax[NB];
__device__ int                g_arrive[NB];
__device__ int                g_flag[NB];
__device__ float              g_L[NB];

// monotone float->uint key (total order matching float compare)
__device__ __forceinline__ unsigned int fkey(float f) {
    unsigned int u = __float_as_uint(f);
    return (u & 0x80000000u) ? ~u : (u | 0x80000000u);
}

// ---------------------------------------------------------------------------
// One kernel, 1024 CTAs x 256 threads, all co-resident (8 blocks/SM regs,
// 12.7KB smem -> >=1184 slots >= 1024), so per-batch spins cannot deadlock.
//
// CTA g belongs to batch b = g>>4.
// Stage A: per-(row,stream) sumexp + draft-token prob; row=g>>1, stream=g&1.
// Per-batch handoff: 16th finisher of batch b runs the accept logic
// (phase2) for b, resets b's stage-B scratch, releases g_go[b].
// Stage B: chunk g&15 of the selected row; y staged in smem; partial
// sumexp/argmax combined via atomics; last arriver finalizes L + token.
// No chip-wide barrier anywhere -> batches pipeline through both stages.
// ---------------------------------------------------------------------------
__global__ __launch_bounds__(256, 8)
void fused_kernel(const float* __restrict__ tgt,
                  const float* __restrict__ base,
                  const float* __restrict__ steer,
                  const int*   __restrict__ draft,
                  const int*   __restrict__ ndraft,
                  float U, float W,
                  float* __restrict__ out)
{
    const int TPB = 256;
    const int tid = threadIdx.x;
    const int g   = blockIdx.x;
    const int b   = g >> 4;                  // batch this CTA serves

    __shared__ float sy[CHUNK];              // stage B staging
    __shared__ float shs[TPB / 32];
    __shared__ float shm[TPB / 32];
    __shared__ int   shi[TPB / 32];
    __shared__ float sh_L;
    __shared__ int   isLeader;

    // ======================= Stage A: phase1 =============================
    {
        const int row    = g >> 1;
        const int stream = g & 1;
        const float* __restrict__ src =
            (stream ? base : tgt) + (size_t)row * NV;

        const int pre = (4 - ((row * NV) & 3)) & 3;   // align to 16B
        float s0 = 0.f, s1 = 0.f, s2 = 0.f, s3 = 0.f;
        if (tid < pre) s0 += __expf(src[tid]);

        const int nvec = (NV - pre) >> 2;
        const float4* __restrict__ pv = reinterpret_cast<const float4*>(src + pre);
        #pragma unroll 4
        for (int i = tid; i < nvec; i += TPB) {
            float4 v = pv[i];
            s0 += __expf(v.x); s1 += __expf(v.y);
            s2 += __expf(v.z); s3 += __expf(v.w);
        }
        const int done = pre + (nvec << 2);
        if (tid < NV - done) s1 += __expf(src[done + tid]);

        float s = (s0 + s1) + (s2 + s3);
        #pragma unroll
        for (int o = 16; o > 0; o >>= 1) s += __shfl_down_sync(0xffffffffu, s, o);
        if ((tid & 31) == 0) shs[tid >> 5] = s;
        __syncthreads();
        if (tid == 0) {
            float tot = 0.f;
            #pragma unroll
            for (int w = 0; w < TPB / 32; ++w) tot += shs[w];
            const int idx = draft[row];
            g_p[stream * NR + row] = expf(src[idx]) / tot;
        }
    }

    // ============ Per-batch handoff: phase2 by the 16th finisher =========
    __threadfence();
    if (tid == 0) {
        const int c = atomicAdd(&g_doneA[b], 1);
        isLeader = (c == NCPR - 1);
        if (isLeader) g_doneA[b] = 0;          // self-reset for next replay
    }
    __syncthreads();
    if (isLeader) {
        if (tid == 0) {
            __threadfence();                   // acquire all 16 CTAs' g_p
            const int num = ndraft[b];
            int cnt = 0;
            for (int k = 0; k < NK; ++k) {
                if (k >= num) break;                          // valid
                const float pl = g_p[b * NK + k];
                const float pb = g_p[NR + b * NK + k];
                if (!(pl > 0.6f * (pb + 1e-10f))) break;      // accept test
                ++cnt;
            }

            for (int k = 0; k < NK; ++k)
                out[b * (NK + 1) + k] = (k < cnt) ? (float)draft[b * NK + k] : -1.0f;
            out[b * (NK + 1) + NK] = -1.0f;                   // bonus (disabled)
            out[OUT_TOK + b] = (float)cnt;                    // cnt output

            const int rp = cnt < (NK - 1) ? cnt : (NK - 1);
            g_sel[b]  = b * NK + rp;
            g_fill[b] = (cnt < num) ? (b * (NK + 1) + cnt) : -1;

            // reset batch b's stage-B scratch for this replay
            g_sum[b]    = 0.f;
            g_amax[b]   = 0ull;
            g_arrive[b] = 0;
            g_flag[b]   = 0;
            __threadfence();
            atomicExch(&g_go[b], 1);           // release batch b
        }
    } else if (tid == 0) {
        while (atomicAdd(&g_go[b], 0) == 0) __nanosleep(32);
    }
    __syncthreads();
    __threadfence();                            // acquire g_sel/g_fill

    // ======================= Stage B: phase3 =============================
    {
        const int chunk = g & 15;
        const int row = g_sel[b];
        const int c0 = chunk * CHUNK;
        const int c1 = (c0 + CHUNK < NV) ? (c0 + CHUNK) : NV;
        const size_t rb = (size_t)row * NV;
        const float* __restrict__ pt = tgt   + rb;
        const float* __restrict__ pb = base  + rb;
        const float* __restrict__ ps = steer + rb;

        float m = -INFINITY; int mi = 0; float s = 0.f;

        const int pre = (4 - (int)((rb + c0) & 3)) & 3;
        if (tid < pre && c0 + tid < c1) {
            const int e = c0 + tid;
            float t = pt[e];  if (isnan(t))  t  = -100.f;
            float bb = pb[e]; if (isnan(bb)) bb = -100.f;
            float ss = ps[e]; if (isnan(ss)) ss = -100.f;
            const float y = U * t + W * (ss - bb);
            sy[e - c0] = y; s += __expf(y);
            if (y > m) { m = y; mi = e; }
        }

        const int nvec = (c1 - c0 - pre) >> 2;
        const float4* __restrict__ vt = reinterpret_cast<const float4*>(pt + c0 + pre);
        const float4* __restrict__ vb = reinterpret_cast<const float4*>(pb + c0 + pre);
        const float4* __restrict__ vs = reinterpret_cast<const float4*>(ps + c0 + pre);
        #pragma unroll 2
        for (int i = tid; i < nvec; i += TPB) {
            float4 a = vt[i], c = vb[i], d = vs[i];
            if (isnan(a.x)) a.x = -100.f; if (isnan(a.y)) a.y = -100.f;
            if (isnan(a.z)) a.z = -100.f; if (isnan(a.w)) a.w = -100.f;
            if (isnan(c.x)) c.x = -100.f; if (isnan(c.y)) c.y = -100.f;
            if (isnan(c.z)) c.z = -100.f; if (isnan(c.w)) c.w = -100.f;
            if (isnan(d.x)) d.x = -100.f; if (isnan(d.y)) d.y = -100.f;
            if (isnan(d.z)) d.z = -100.f; if (isnan(d.w)) d.w = -100.f;
            const int e = c0 + pre + 4 * i;          // global element index
            const int l = e - c0;                    // smem index
            const float y0 = U * a.x + W * (d.x - c.x);
            const float y1 = U * a.y + W * (d.y - c.y);
            const float y2 = U * a.z + W * (d.z - c.z);
            const float y3 = U * a.w + W * (d.w - c.w);
            sy[l]     = y0; sy[l + 1] = y1;
            sy[l + 2] = y2; sy[l + 3] = y3;
            s += (__expf(y0) + __expf(y1)) + (__expf(y2) + __expf(y3));
            if (y0 > m) { m = y0; mi = e; }
            if (y1 > m) { m = y1; mi = e + 1; }
            if (y2 > m) { m = y2; mi = e + 2; }
            if (y3 > m) { m = y3; mi = e + 3; }
        }
        const int done = c0 + pre + (nvec << 2);
        if (done + tid < c1) {
            const int e = done + tid;
            float t = pt[e];  if (isnan(t))  t  = -100.f;
            float bb = pb[e]; if (isnan(bb)) bb = -100.f;
            float ss = ps[e]; if (isnan(ss)) ss = -100.f;
            const float y = U * t + W * (ss - bb);
            sy[e - c0] = y; s += __expf(y);
            if (y > m) { m = y; mi = e; }
        }

        // block reductions: sum and (max, first-index argmax)
        #pragma unroll
        for (int o = 16; o > 0; o >>= 1) {
            s += __shfl_down_sync(0xffffffffu, s, o);
            float m2 = __shfl_down_sync(0xffffffffu, m, o);
            int   i2 = __shfl_down_sync(0xffffffffu, mi, o);
            if (m2 > m || (m2 == m && i2 < mi)) { m = m2; mi = i2; }
        }
        if ((tid & 31) == 0) { shs[tid >> 5] = s; shm[tid >> 5] = m; shi[tid >> 5] = mi; }
        __syncthreads();

        if (tid == 0) {
            float tot = 0.f;
            float M = shm[0]; int MI = shi[0];
            #pragma unroll
            for (int w = 0; w < TPB / 32; ++w) {
                tot += shs[w];
                if (shm[w] > M || (shm[w] == M && shi[w] < MI)) { M = shm[w]; MI = shi[w]; }
            }
            atomicAdd(&g_sum[b], tot);
            const unsigned long long key =
                ((unsigned long long)fkey(M) << 32) |
                (unsigned long long)(0xFFFFFFFFu - (unsigned int)MI);
            atomicMax(&g_amax[b], key);
            __threadfence();
            const int old = atomicAdd(&g_arrive[b], 1);
            if (old == NCPR - 1) {
                const float L = logf(g_sum[b]);
                g_L[b] = L;
                const int f = g_fill[b];
                if (f >= 0) {
                    const unsigned long long k = g_amax[b];
                    const int idx = (int)(0xFFFFFFFFu - (unsigned int)(k & 0xFFFFFFFFull));
                    out[f] = (float)idx;            // recovered token
                }
                __threadfence();
                atomicExch(&g_flag[b], 1);
                sh_L = L;
            } else {
                while (atomicAdd(&g_flag[b], 0) == 0) __nanosleep(32);
                __threadfence();
                sh_L = g_L[b];
            }
        }
        __syncthreads();
        const float L = sh_L;

        // write normalized log-probs from smem (coalesced)
        float* __restrict__ fo = out + FUSED_OFF + (size_t)b * NV;
        for (int i = c0 + tid; i < c1; i += TPB) fo[i] = sy[i - c0] - L;
    }

    // ============== epilogue: reset g_go[b] for graph replay =============
    __threadfence();
    if (tid == 0) {
        const int c = atomicAdd(&g_cnt2[b], 1);
        if (c == NCPR - 1) {     // all 16 CTAs of batch b passed their spin
            g_cnt2[b] = 0;
            atomicExch(&g_go[b], 0);
        }
    }
}

// ---------------------------------------------------------------------------
extern "C" void kernel_launch(void* const* d_in, const int* in_sizes, int n_in,
                              void* d_out, int out_size)
{
    const float* tgt    = (const float*)d_in[0];
    const float* base   = (const float*)d_in[1];
    const float* steer  = (const float*)d_in[2];
    const int*   draft  = (const int*)d_in[3];
    const int*   ndraft = (const int*)d_in[4];
    // d_in[5] = bonus_token_ids: unused (ENABLE_BONUS == False)
    float* out = (float*)d_out;

    // Collapse the T=20 costeer recursion to scalar coefficients (double).
    // lp_t = log_softmax(u_t * llm_log + v_t * delta); u_t == 1 exactly.
    double Qu = 0.0, u = 1.0, Qv = 0.0, v = 0.0;
    for (int t = 1; t <= 20; ++t) {
        Qu += 2.0 * (u - 1.0);                 // ALPHA * (u - 1)
        Qv += 2.0 * v + 1.5;                   // ALPHA * v + BETA
        const double denom = 2.0 * t + 0.1;    // t*LAM + 1/ETA
        const double un = (2.0 * t + Qu + u / 10.0) / denom;
        const double vn = (Qv + v / 10.0) / denom;
        u = un; v = vn;
    }
    const float Uf = (float)u;
    const float Wf = (float)v;

    fused_kernel<<<GRID, 256>>>(tgt, base, steer, draft, ndraft, Uf, Wf, out);
}

// round 12
// speedup vs baseline: 1.2687x; 1.2215x over previous
#include <cuda_runtime.h>
#include <math.h>

#define NB 64
#define NK 8
#define NV 50257
#define NR (NB*NK)                 // 512 rows
#define OUT_TOK (NB*(NK+1))        // 576
#define FUSED_OFF (OUT_TOK + NB)   // 640

#define GRID (2*NR)                // 1024 CTAs
#define NCPR 16                    // CTAs per batch (stage A and stage B)
#define CHUNK 3144                 // NCPR*CHUNK >= NV; smem ~12.6KB

// Scratch (device globals: no allocation allowed; zero-initialized)
__device__ float g_p[2*NR];        // [0..NR): p_llm, [NR..2NR): p_base
__device__ int   g_sel[NB];        // selected flat row index (b*K + rp)
__device__ int   g_fill[NB];       // output slot for recovered token, or -1
__device__ int   g_doneA[NB];      // per-batch stage A counter (self-reset)
__device__ int   g_go[NB];         // per-batch A->B release flag
__device__ int   g_cnt2[NB];       // per-batch stage B epilogue counter
// stage B cross-CTA reduction scratch (reset by batch's phase2 leader)
__device__ float              g_sum[NB];
__device__ unsigned long long g_amax[NB];
__device__ int                g_arrive[NB];
__device__ int                g_flag[NB];
__device__ float              g_L[NB];

// monotone float->uint key (total order matching float compare)
__device__ __forceinline__ unsigned int fkey(float f) {
    unsigned int u = __float_as_uint(f);
    return (u & 0x80000000u) ? ~u : (u | 0x80000000u);
}

// ---------------------------------------------------------------------------
// One kernel, 1024 CTAs x 256 threads, all co-resident (8 blocks/SM regs,
// 12.7KB smem -> 1184 slots >= 1024), so per-batch spins cannot deadlock.
//
// CTA g belongs to batch b = g>>4; stage A covers row=g>>1 (k=row&7),
// stream=g&1.
//
// KEY: stage A work for k >= num_draft_tokens[b] is SKIPPED — the accept
// prefix-product masks those positions to 0 regardless of p, and phase2's
// loop breaks before reading their g_p. Expected read volume drops ~44%.
// The skip condition is CTA-uniform (b, k depend only on blockIdx), so the
// __syncthreads() inside the guarded block cannot diverge.
//
// Per-batch handoff: 16th arriver of batch b runs the accept logic
// (phase2) for b, resets b's stage-B scratch, releases g_go[b].
// Stage B: chunk g&15 of the selected row; y staged in smem; partial
// sumexp/argmax combined via atomics; last arriver finalizes L + token.
// No chip-wide barrier -> batches pipeline through both stages.
// ---------------------------------------------------------------------------
__global__ __launch_bounds__(256, 8)
void fused_kernel(const float* __restrict__ tgt,
                  const float* __restrict__ base,
                  const float* __restrict__ steer,
                  const int*   __restrict__ draft,
                  const int*   __restrict__ ndraft,
                  float U, float W,
                  float* __restrict__ out)
{
    const int TPB = 256;
    const int tid = threadIdx.x;
    const int g   = blockIdx.x;
    const int b   = g >> 4;                  // batch this CTA serves

    __shared__ float sy[CHUNK];              // stage B staging
    __shared__ float shs[TPB / 32];
    __shared__ float shm[TPB / 32];
    __shared__ int   shi[TPB / 32];
    __shared__ float sh_L;
    __shared__ int   isLeader;

    // ======================= Stage A: phase1 =============================
    {
        const int row    = g >> 1;
        const int stream = g & 1;
        const int k      = row & (NK - 1);

        // Skip rows the accept logic can never consume (k >= num[b]).
        if (k < ndraft[b]) {
            const float* __restrict__ src =
                (stream ? base : tgt) + (size_t)row * NV;

            const int pre = (4 - ((row * NV) & 3)) & 3;   // align to 16B
            float s0 = 0.f, s1 = 0.f, s2 = 0.f, s3 = 0.f;
            if (tid < pre) s0 += __expf(src[tid]);

            const int nvec = (NV - pre) >> 2;
            const float4* __restrict__ pv = reinterpret_cast<const float4*>(src + pre);
            #pragma unroll 4
            for (int i = tid; i < nvec; i += TPB) {
                float4 v = pv[i];
                s0 += __expf(v.x); s1 += __expf(v.y);
                s2 += __expf(v.z); s3 += __expf(v.w);
            }
            const int done = pre + (nvec << 2);
            if (tid < NV - done) s1 += __expf(src[done + tid]);

            float s = (s0 + s1) + (s2 + s3);
            #pragma unroll
            for (int o = 16; o > 0; o >>= 1) s += __shfl_down_sync(0xffffffffu, s, o);
            if ((tid & 31) == 0) shs[tid >> 5] = s;
            __syncthreads();
            if (tid == 0) {
                float tot = 0.f;
                #pragma unroll
                for (int w = 0; w < TPB / 32; ++w) tot += shs[w];
                const int idx = draft[row];
                g_p[stream * NR + row] = expf(src[idx]) / tot;
            }
        }
    }

    // ============ Per-batch handoff: phase2 by the 16th arriver ==========
    __threadfence();
    if (tid == 0) {
        const int c = atomicAdd(&g_doneA[b], 1);
        isLeader = (c == NCPR - 1);
        if (isLeader) g_doneA[b] = 0;          // self-reset for next replay
    }
    __syncthreads();
    if (isLeader) {
        if (tid == 0) {
            __threadfence();                   // acquire all 16 CTAs' g_p
            const int num = ndraft[b];
            int cnt = 0;
            for (int k = 0; k < NK; ++k) {
                if (k >= num) break;                          // valid
                const float pl = g_p[b * NK + k];
                const float pb = g_p[NR + b * NK + k];
                if (!(pl > 0.6f * (pb + 1e-10f))) break;      // accept test
                ++cnt;
            }

            for (int k = 0; k < NK; ++k)
                out[b * (NK + 1) + k] = (k < cnt) ? (float)draft[b * NK + k] : -1.0f;
            out[b * (NK + 1) + NK] = -1.0f;                   // bonus (disabled)
            out[OUT_TOK + b] = (float)cnt;                    // cnt output

            const int rp = cnt < (NK - 1) ? cnt : (NK - 1);
            g_sel[b]  = b * NK + rp;
            g_fill[b] = (cnt < num) ? (b * (NK + 1) + cnt) : -1;

            // reset batch b's stage-B scratch for this replay
            g_sum[b]    = 0.f;
            g_amax[b]   = 0ull;
            g_arrive[b] = 0;
            g_flag[b]   = 0;
            __threadfence();
            atomicExch(&g_go[b], 1);           // release batch b
        }
    } else if (tid == 0) {
        volatile int* go = &g_go[b];
        while (*go == 0) __nanosleep(32);
    }
    __syncthreads();
    __threadfence();                            // acquire g_sel/g_fill

    // ======================= Stage B: phase3 =============================
    {
        const int chunk = g & 15;
        const int row = g_sel[b];
        const int c0 = chunk * CHUNK;
        const int c1 = (c0 + CHUNK < NV) ? (c0 + CHUNK) : NV;
        const size_t rb = (size_t)row * NV;
        const float* __restrict__ pt = tgt   + rb;
        const float* __restrict__ pb = base  + rb;
        const float* __restrict__ ps = steer + rb;

        float m = -INFINITY; int mi = 0; float s = 0.f;

        const int pre = (4 - (int)((rb + c0) & 3)) & 3;
        if (tid < pre && c0 + tid < c1) {
            const int e = c0 + tid;
            float t = pt[e];  if (isnan(t))  t  = -100.f;
            float bb = pb[e]; if (isnan(bb)) bb = -100.f;
            float ss = ps[e]; if (isnan(ss)) ss = -100.f;
            const float y = U * t + W * (ss - bb);
            sy[e - c0] = y; s += __expf(y);
            if (y > m) { m = y; mi = e; }
        }

        const int nvec = (c1 - c0 - pre) >> 2;
        const float4* __restrict__ vt = reinterpret_cast<const float4*>(pt + c0 + pre);
        const float4* __restrict__ vb = reinterpret_cast<const float4*>(pb + c0 + pre);
        const float4* __restrict__ vs = reinterpret_cast<const float4*>(ps + c0 + pre);
        #pragma unroll 2
        for (int i = tid; i < nvec; i += TPB) {
            float4 a = vt[i], c = vb[i], d = vs[i];
            if (isnan(a.x)) a.x = -100.f; if (isnan(a.y)) a.y = -100.f;
            if (isnan(a.z)) a.z = -100.f; if (isnan(a.w)) a.w = -100.f;
            if (isnan(c.x)) c.x = -100.f; if (isnan(c.y)) c.y = -100.f;
            if (isnan(c.z)) c.z = -100.f; if (isnan(c.w)) c.w = -100.f;
            if (isnan(d.x)) d.x = -100.f; if (isnan(d.y)) d.y = -100.f;
            if (isnan(d.z)) d.z = -100.f; if (isnan(d.w)) d.w = -100.f;
            const int e = c0 + pre + 4 * i;          // global element index
            const int l = e - c0;                    // smem index
            const float y0 = U * a.x + W * (d.x - c.x);
            const float y1 = U * a.y + W * (d.y - c.y);
            const float y2 = U * a.z + W * (d.z - c.z);
            const float y3 = U * a.w + W * (d.w - c.w);
            sy[l]     = y0; sy[l + 1] = y1;
            sy[l + 2] = y2; sy[l + 3] = y3;
            s += (__expf(y0) + __expf(y1)) + (__expf(y2) + __expf(y3));
            if (y0 > m) { m = y0; mi = e; }
            if (y1 > m) { m = y1; mi = e + 1; }
            if (y2 > m) { m = y2; mi = e + 2; }
            if (y3 > m) { m = y3; mi = e + 3; }
        }
        const int done = c0 + pre + (nvec << 2);
        if (done + tid < c1) {
            const int e = done + tid;
            float t = pt[e];  if (isnan(t))  t  = -100.f;
            float bb = pb[e]; if (isnan(bb)) bb = -100.f;
            float ss = ps[e]; if (isnan(ss)) ss = -100.f;
            const float y = U * t + W * (ss - bb);
            sy[e - c0] = y; s += __expf(y);
            if (y > m) { m = y; mi = e; }
        }

        // block reductions: sum and (max, first-index argmax)
        #pragma unroll
        for (int o = 16; o > 0; o >>= 1) {
            s += __shfl_down_sync(0xffffffffu, s, o);
            float m2 = __shfl_down_sync(0xffffffffu, m, o);
            int   i2 = __shfl_down_sync(0xffffffffu, mi, o);
            if (m2 > m || (m2 == m && i2 < mi)) { m = m2; mi = i2; }
        }
        if ((tid & 31) == 0) { shs[tid >> 5] = s; shm[tid >> 5] = m; shi[tid >> 5] = mi; }
        __syncthreads();

        if (tid == 0) {
            float tot = 0.f;
            float M = shm[0]; int MI = shi[0];
            #pragma unroll
            for (int w = 0; w < TPB / 32; ++w) {
                tot += shs[w];
                if (shm[w] > M || (shm[w] == M && shi[w] < MI)) { M = shm[w]; MI = shi[w]; }
            }
            atomicAdd(&g_sum[b], tot);
            const unsigned long long key =
                ((unsigned long long)fkey(M) << 32) |
                (unsigned long long)(0xFFFFFFFFu - (unsigned int)MI);
            atomicMax(&g_amax[b], key);
            __threadfence();
            const int old = atomicAdd(&g_arrive[b], 1);
            if (old == NCPR - 1) {
                const float L = logf(g_sum[b]);
                g_L[b] = L;
                const int f = g_fill[b];
                if (f >= 0) {
                    const unsigned long long k = g_amax[b];
                    const int idx = (int)(0xFFFFFFFFu - (unsigned int)(k & 0xFFFFFFFFull));
                    out[f] = (float)idx;            // recovered token
                }
                __threadfence();
                atomicExch(&g_flag[b], 1);
                sh_L = L;
            } else {
                volatile int* fl = &g_flag[b];
                while (*fl == 0) __nanosleep(32);
                __threadfence();
                sh_L = g_L[b];
            }
        }
        __syncthreads();
        const float L = sh_L;

        // write normalized log-probs from smem (coalesced)
        float* __restrict__ fo = out + FUSED_OFF + (size_t)b * NV;
        for (int i = c0 + tid; i < c1; i += TPB) fo[i] = sy[i - c0] - L;
    }

    // ============== epilogue: reset g_go[b] for graph replay =============
    __threadfence();
    if (tid == 0) {
        const int c = atomicAdd(&g_cnt2[b], 1);
        if (c == NCPR - 1) {     // all 16 CTAs of batch b passed their spin
            g_cnt2[b] = 0;
            atomicExch(&g_go[b], 0);
        }
    }
}

// ---------------------------------------------------------------------------
extern "C" void kernel_launch(void* const* d_in, const int* in_sizes, int n_in,
                              void* d_out, int out_size)
{
    const float* tgt    = (const float*)d_in[0];
    const float* base   = (const float*)d_in[1];
    const float* steer  = (const float*)d_in[2];
    const int*   draft  = (const int*)d_in[3];
    const int*   ndraft = (const int*)d_in[4];
    // d_in[5] = bonus_token_ids: unused (ENABLE_BONUS == False)
    float* out = (float*)d_out;

    // Collapse the T=20 costeer recursion to scalar coefficients (double).
    // lp_t = log_softmax(u_t * llm_log + v_t * delta); u_t == 1 exactly.
    double Qu = 0.0, u = 1.0, Qv = 0.0, v = 0.0;
    for (int t = 1; t <= 20; ++t) {
        Qu += 2.0 * (u - 1.0);                 // ALPHA * (u - 1)
        Qv += 2.0 * v + 1.5;                   // ALPHA * v + BETA
        const double denom = 2.0 * t + 0.1;    // t*LAM + 1/ETA
        const double un = (2.0 * t + Qu + u / 10.0) / denom;
        const double vn = (Qv + v / 10.0) / denom;
        u = un; v = vn;
    }
    const float Uf = (float)u;
    const float Wf = (float)v;

    fused_kernel<<<GRID, 256>>>(tgt, base, steer, draft, ndraft, Uf, Wf, out);
}